// round 11
// baseline (speedup 1.0000x reference)
#include <cuda_runtime.h>
#include <cuda_bf16.h>
#include <math.h>
#include <stdint.h>

#define Bq 2
#define Nq 2048
#define Dq 256
#define Hq 8
#define HDq 32
#define DFFq 1024
#define ROWS (Bq*Nq)          // 4096

// ---------------- scratch (device globals; no allocs allowed) ----------------
__device__ __nv_bfloat16 g_qkvwh[768 * 256],  g_qkvwl[768 * 256];   // [N,K] planes
__device__ __nv_bfloat16 g_projwh[256 * 256], g_projwl[256 * 256];
__device__ __nv_bfloat16 g_fc1wh[1024 * 256], g_fc1wl[1024 * 256];
__device__ __nv_bfloat16 g_fc2wh[256 * 1024], g_fc2wl[256 * 1024];
__device__ __nv_bfloat16 g_qkvh[ROWS * 768],  g_qkvl[ROWS * 768];
__device__ __nv_bfloat16 g_atth[ROWS * Dq],   g_attl[ROWS * Dq];
__device__ __nv_bfloat16 g_neth[ROWS * Dq],   g_netl[ROWS * Dq];
__device__ __nv_bfloat16 g_h1h[ROWS * DFFq],  g_h1l[ROWS * DFFq];
__device__ float g_proj[ROWS * Dq];   // pre-LN fp32
__device__ float g_net[ROWS * Dq];    // shortcut fp32

// ---------------- helpers ------------------------------------------------------
__device__ __forceinline__ uint32_t smem_u32(const void* p) {
    uint32_t a;
    asm("{ .reg .u64 t; cvta.to.shared.u64 t, %1; cvt.u32.u64 %0, t; }"
        : "=r"(a) : "l"(p));
    return a;
}
__device__ __forceinline__ void cp16(uint32_t dst, const void* src) {
    asm volatile("cp.async.cg.shared.global [%0], [%1], 16;" :: "r"(dst), "l"(src));
}
#define CP_COMMIT() asm volatile("cp.async.commit_group;" ::: "memory")
#define CP_WAIT0()  asm volatile("cp.async.wait_group 0;" ::: "memory")

__device__ __forceinline__ float ex2f(float x) {
    float y; asm("ex2.approx.f32 %0, %1;" : "=f"(y) : "f"(x)); return y;
}
__device__ __forceinline__ void split4(float4 a, uint32_t& h01, uint32_t& h23,
                                       uint32_t& g01, uint32_t& g23) {
    asm("cvt.rn.bf16x2.f32 %0, %1, %2;" : "=r"(h01) : "f"(a.y), "f"(a.x));
    asm("cvt.rn.bf16x2.f32 %0, %1, %2;" : "=r"(h23) : "f"(a.w), "f"(a.z));
    float l0 = a.x - __int_as_float(h01 << 16);
    float l1 = a.y - __int_as_float(h01 & 0xffff0000u);
    float l2 = a.z - __int_as_float(h23 << 16);
    float l3 = a.w - __int_as_float(h23 & 0xffff0000u);
    asm("cvt.rn.bf16x2.f32 %0, %1, %2;" : "=r"(g01) : "f"(l1), "f"(l0));
    asm("cvt.rn.bf16x2.f32 %0, %1, %2;" : "=r"(g23) : "f"(l3), "f"(l2));
}
__device__ __forceinline__ void split2(float a, float b, uint32_t& h, uint32_t& g) {
    asm("cvt.rn.bf16x2.f32 %0, %1, %2;" : "=r"(h) : "f"(b), "f"(a));
    float la = a - __int_as_float(h << 16);
    float lb = b - __int_as_float(h & 0xffff0000u);
    asm("cvt.rn.bf16x2.f32 %0, %1, %2;" : "=r"(g) : "f"(lb), "f"(la));
}

#define LDSM4(r, addr) \
    asm volatile("ldmatrix.sync.aligned.m8n8.x4.shared.b16 {%0,%1,%2,%3}, [%4];" \
        : "=r"((r)[0]), "=r"((r)[1]), "=r"((r)[2]), "=r"((r)[3]) : "r"(addr))
#define LDSM4_T(r, addr) \
    asm volatile("ldmatrix.sync.aligned.m8n8.x4.trans.shared.b16 {%0,%1,%2,%3}, [%4];" \
        : "=r"((r)[0]), "=r"((r)[1]), "=r"((r)[2]), "=r"((r)[3]) : "r"(addr))
#define MMA16816(d, a, b0, b1) \
    asm volatile("mma.sync.aligned.m16n8k16.row.col.f32.bf16.bf16.f32 " \
        "{%0,%1,%2,%3}, {%4,%5,%6,%7}, {%8,%9}, {%0,%1,%2,%3};" \
        : "+f"((d)[0]), "+f"((d)[1]), "+f"((d)[2]), "+f"((d)[3]) \
        : "r"((a)[0]), "r"((a)[1]), "r"((a)[2]), "r"((a)[3]), "r"(b0), "r"(b1))

#define ASTRIDE 144

// ================= fused weight prep: transpose + bf16 hi/lo split ===========
__global__ void __launch_bounds__(256)
prep_w(const float* __restrict__ qkv_w, const float* __restrict__ proj_w,
       const float* __restrict__ fc1_w, const float* __restrict__ fc2_w,
       __nv_bfloat16* __restrict__ qwh, __nv_bfloat16* __restrict__ qwl,
       __nv_bfloat16* __restrict__ pwh, __nv_bfloat16* __restrict__ pwl,
       __nv_bfloat16* __restrict__ f1h, __nv_bfloat16* __restrict__ f1l,
       __nv_bfloat16* __restrict__ f2h, __nv_bfloat16* __restrict__ f2l)
{
    __shared__ float tile[32][33];
    const int bid = blockIdx.x;
    const float* W; __nv_bfloat16 *th, *tl; int K, N, tid;
    if (bid < 192)      { W = qkv_w;  th = qwh; tl = qwl; K = 256;  N = 768;  tid = bid; }
    else if (bid < 256) { W = proj_w; th = pwh; tl = pwl; K = 256;  N = 256;  tid = bid - 192; }
    else if (bid < 512) { W = fc1_w;  th = f1h; tl = f1l; K = 256;  N = 1024; tid = bid - 256; }
    else                { W = fc2_w;  th = f2h; tl = f2l; K = 1024; N = 256;  tid = bid - 512; }
    const int nt = N >> 5;
    const int nb = (tid % nt) << 5, kb = (tid / nt) << 5;
    const int tx = threadIdx.x & 31, ty = threadIdx.x >> 5;   // 32 x 8
    #pragma unroll
    for (int i = 0; i < 4; i++)
        tile[ty + 8 * i][tx] = W[(size_t)(kb + ty + 8 * i) * N + nb + tx];
    __syncthreads();
    #pragma unroll
    for (int i = 0; i < 4; i++) {
        const int n = nb + ty + 8 * i, k = kb + tx;
        float v = tile[tx][ty + 8 * i];
        __nv_bfloat16 h = __float2bfloat16(v);
        th[(size_t)n * K + k] = h;
        tl[(size_t)n * K + k] = __float2bfloat16(v - __bfloat162float(h));
    }
}

// ================= bf16x3-split GEMM, cp.async double-buffered ===============
// C[M,N] = A[M,K]@B^T. CTA tile (MT*64)x(NT*32), BK=32, 256 threads (4m x 2n).
// MT in {1,2}: warp m = MT*16.  NT in {1,2}: warp n = NT*16, BN = NT*32.
// AMODE 0: A planes (cp.async). AMODE 1: A fp32 reg-staged + split (MT=2 only).
// OUTMODE 0: fp32 C (+bias)(+res). OUTMODE 1: planes Ch/Cl (+bias).
template<int MT, int NT, int AMODE, int OUTMODE>
__global__ void __launch_bounds__(256)
gemm_p(const __nv_bfloat16* __restrict__ Ah, const __nv_bfloat16* __restrict__ Al,
       const float* __restrict__ Af,
       const __nv_bfloat16* __restrict__ Bh, const __nv_bfloat16* __restrict__ Bl,
       const float* __restrict__ bias, const float* __restrict__ res,
       float* __restrict__ C, __nv_bfloat16* __restrict__ Ch,
       __nv_bfloat16* __restrict__ Cl, int M, int N, int K)
{
    constexpr int BM = MT * 64;
    constexpr int BN = NT * 32;
    constexpr int AB = BM * ASTRIDE;
    constexpr int BNB = BN * ASTRIDE;
    extern __shared__ char smem[];
    const uint32_t aB = smem_u32(smem);
    const uint32_t bB = aB + 2 * AB;

    const int t    = threadIdx.x;
    const int wid  = t >> 5, lane = t & 31;
    const int bm   = blockIdx.y * BM;
    const int bn   = blockIdx.x * BN;
    const int wm   = (wid & 3) * (MT * 16);
    const int wn   = (wid >> 2) * (NT * 16);
    const int ar   = t >> 2, asg = t & 3;

    float acc[MT][2 * NT][4];
    #pragma unroll
    for (int i = 0; i < MT; i++)
        #pragma unroll
        for (int j = 0; j < 2 * NT; j++)
            #pragma unroll
            for (int k = 0; k < 4; k++) acc[i][j][k] = 0.f;

    const uint32_t a_row = wm + (lane & 15);
    const uint32_t a_off = (lane >> 4) << 4;
    const uint32_t b_row = wn + (lane & 7) + ((lane >> 4) << 3);
    const uint32_t b_off = ((lane >> 3) & 1) << 4;

    float4 apf[4];

    auto cpA = [&](int buf, int k0) {
        const uint32_t d0 = aB + buf * AB;
        #pragma unroll
        for (int i = 0; i < MT; i++) {
            const int r = ar + i * 64;
            const size_t go = (size_t)(bm + r) * K + k0 + asg * 8;
            uint32_t dst = d0 + r * ASTRIDE + asg * 16;
            cp16(dst, Ah + go);
            cp16(dst + 64, Al + go);
        }
    };
    auto cpB = [&](int buf, int k0) {
        if (NT == 2 || t < 128) {
            const size_t go = (size_t)(bn + ar) * K + k0 + asg * 8;
            uint32_t dst = bB + buf * BNB + ar * ASTRIDE + asg * 16;
            cp16(dst, Bh + go);
            cp16(dst + 64, Bl + go);
        }
    };
    auto ldgA = [&](int k0) {
        #pragma unroll
        for (int i = 0; i < 4; i++) {
            int idx = i * 256 + t;
            int r = idx >> 3, q = (idx & 7) << 2;
            apf[i] = *(const float4*)&Af[(size_t)(bm + r) * K + k0 + q];
        }
    };
    auto stsA = [&](int buf) {
        const uint32_t d0 = aB + buf * AB;
        #pragma unroll
        for (int i = 0; i < 4; i++) {
            int idx = i * 256 + t;
            int r = idx >> 3, q = (idx & 7) << 2;
            uint32_t h01, h23, g01, g23;
            split4(apf[i], h01, h23, g01, g23);
            uint32_t ad = d0 + r * ASTRIDE + (q << 1);
            asm volatile("st.shared.v2.b32 [%0], {%1,%2};" :: "r"(ad), "r"(h01), "r"(h23));
            asm volatile("st.shared.v2.b32 [%0], {%1,%2};" :: "r"(ad + 64), "r"(g01), "r"(g23));
        }
    };

    if (AMODE == 0) cpA(0, 0); else { ldgA(0); stsA(0); }
    cpB(0, 0);
    CP_COMMIT();
    CP_WAIT0();
    __syncthreads();

    const int T = K >> 5;
    int cur = 0;
    for (int i = 0; i < T; i++) {
        const bool more = (i + 1 < T);
        if (more) {
            const int kn = (i + 1) << 5;
            if (AMODE == 0) cpA(cur ^ 1, kn); else ldgA(kn);
            cpB(cur ^ 1, kn);
            CP_COMMIT();
        }
        const uint32_t aC = aB + cur * AB;
        const uint32_t bC = bB + cur * BNB;
        #pragma unroll
        for (int ks = 0; ks < 2; ks++) {
            uint32_t ah[MT][4], al2[MT][4], bh[NT][4], bl[NT][4];
            #pragma unroll
            for (int mt = 0; mt < MT; mt++) {
                uint32_t ad = aC + (a_row + mt * 16) * ASTRIDE + (ks << 5) + a_off;
                LDSM4(ah[mt], ad);
                LDSM4(al2[mt], ad + 64);
            }
            #pragma unroll
            for (int gg = 0; gg < NT; gg++) {
                uint32_t bd = bC + (b_row + gg * 16) * ASTRIDE + (ks << 5) + b_off;
                LDSM4(bh[gg], bd);
                LDSM4(bl[gg], bd + 64);
            }
            #pragma unroll
            for (int mt = 0; mt < MT; mt++)
                #pragma unroll
                for (int nt = 0; nt < 2 * NT; nt++) {
                    const int gsel = nt >> 1, rsel = (nt & 1) << 1;
                    uint32_t bh0 = bh[gsel][rsel], bh1 = bh[gsel][rsel + 1];
                    uint32_t bl0 = bl[gsel][rsel], bl1 = bl[gsel][rsel + 1];
                    MMA16816(acc[mt][nt], ah[mt], bh0, bh1);
                    MMA16816(acc[mt][nt], ah[mt], bl0, bl1);
                    MMA16816(acc[mt][nt], al2[mt], bh0, bh1);
                }
        }
        if (more) {
            if (AMODE == 1) stsA(cur ^ 1);
            CP_WAIT0();
            __syncthreads();
            cur ^= 1;
        }
    }

    const int gr = lane >> 2, c2 = (lane & 3) << 1;
    #pragma unroll
    for (int mt = 0; mt < MT; mt++)
        #pragma unroll
        for (int nt = 0; nt < 2 * NT; nt++) {
            const int row = bm + wm + mt * 16 + gr;
            const int col = bn + wn + nt * 8 + c2;
            float2 v0 = make_float2(acc[mt][nt][0], acc[mt][nt][1]);
            float2 v1 = make_float2(acc[mt][nt][2], acc[mt][nt][3]);
            if (bias) {
                float2 bb = *(const float2*)&bias[col];
                v0.x += bb.x; v0.y += bb.y; v1.x += bb.x; v1.y += bb.y;
            }
            if (OUTMODE == 0) {
                if (res) {
                    float2 r0 = *(const float2*)&res[(size_t)row * N + col];
                    float2 r1 = *(const float2*)&res[(size_t)(row + 8) * N + col];
                    v0.x += r0.x; v0.y += r0.y; v1.x += r1.x; v1.y += r1.y;
                }
                *(float2*)&C[(size_t)row * N + col] = v0;
                *(float2*)&C[(size_t)(row + 8) * N + col] = v1;
            } else {
                uint32_t h, g;
                split2(v0.x, v0.y, h, g);
                *(uint32_t*)&Ch[(size_t)row * N + col] = h;
                *(uint32_t*)&Cl[(size_t)row * N + col] = g;
                split2(v1.x, v1.y, h, g);
                *(uint32_t*)&Ch[(size_t)(row + 8) * N + col] = h;
                *(uint32_t*)&Cl[(size_t)(row + 8) * N + col] = g;
            }
        }
}
#define GEMM_SMEM_22 (2 * (128 * ASTRIDE) + 2 * (64 * ASTRIDE))   // 55296
#define GEMM_SMEM_11 (2 * (64 * ASTRIDE) + 2 * (32 * ASTRIDE))    // 27648

// ================= tensor-core flash attention (R8 config) ===================
// grid (Nq/128, B*H), 256 threads = 8 warps x m16. KV tiles of 64 keys.
#define SCALE2 (5.656854249492381f * 1.4426950408889634f)
#define ABYTES128 (128 * ASTRIDE)
#define KVBYTES (64 * ASTRIDE)
#define ATTN_SMEM (ABYTES128 + 4 * KVBYTES)       // 55296
__global__ void __launch_bounds__(256)
attn_mma(const __nv_bfloat16* __restrict__ qkvh,
         const __nv_bfloat16* __restrict__ qkvl,
         __nv_bfloat16* __restrict__ outh, __nv_bfloat16* __restrict__ outl)
{
    extern __shared__ char smem[];
    const uint32_t qB = smem_u32(smem);
    const uint32_t kB0 = qB + ABYTES128;
    const uint32_t vB0 = kB0 + 2 * KVBYTES;

    const int t = threadIdx.x, wid = t >> 5, lane = t & 31;
    const int q0 = blockIdx.x * 128;
    const int bh = blockIdx.y;
    const int b = bh >> 3, h = bh & 7;
    const size_t rowbase = (size_t)b * Nq;
    const __nv_bfloat16* qh = qkvh + rowbase * 768 + h * HDq;
    const __nv_bfloat16* ql = qkvl + rowbase * 768 + h * HDq;

    const int ar = t >> 2, asg = t & 3;

    auto cpKV = [&](int kt, int buf) {
        const size_t go = (size_t)(kt + ar) * 768 + asg * 8;
        uint32_t kd = kB0 + buf * KVBYTES + ar * ASTRIDE + asg * 16;
        cp16(kd,      qh + go + 256);
        cp16(kd + 64, ql + go + 256);
        uint32_t vd = vB0 + buf * KVBYTES + ar * ASTRIDE + asg * 16;
        cp16(vd,      qh + go + 512);
        cp16(vd + 64, ql + go + 512);
    };

    // Q tile: 128 x 32, both planes
    #pragma unroll
    for (int i = 0; i < 2; i++) {
        const int r = ar + i * 64;
        const size_t go = (size_t)(q0 + r) * 768 + asg * 8;
        uint32_t dst = qB + r * ASTRIDE + asg * 16;
        cp16(dst, qh + go);
        cp16(dst + 64, ql + go);
    }
    cpKV(0, 0);
    CP_COMMIT();

    const int wm16 = wid * 16;
    const uint32_t a_row = wm16 + (lane & 15);
    const uint32_t a_off = (lane >> 4) << 4;
    const uint32_t kb_part = (lane & 7) + ((lane >> 4) << 3);
    const uint32_t kb_off  = ((lane >> 3) & 1) << 4;
    const uint32_t v_row = (lane & 7) + (((lane >> 3) & 1) << 3);
    const uint32_t v_off = (lane >> 4) << 4;

    float m0 = -1e30f, m1 = -1e30f, l0 = 0.f, l1 = 0.f;
    float O[4][4];
    #pragma unroll
    for (int j = 0; j < 4; j++)
        #pragma unroll
        for (int i = 0; i < 4; i++) O[j][i] = 0.f;

    CP_WAIT0();
    __syncthreads();

    int cur = 0;
    for (int kt = 0; kt < Nq; kt += 64) {
        const bool more = (kt + 64 < Nq);
        if (more) { cpKV(kt + 64, cur ^ 1); CP_COMMIT(); }

        const uint32_t kC = kB0 + cur * KVBYTES;
        const uint32_t vC = vB0 + cur * KVBYTES;

        // S = Q K^T (3-term split)
        float S[8][4];
        #pragma unroll
        for (int nt = 0; nt < 8; nt++)
            #pragma unroll
            for (int i = 0; i < 4; i++) S[nt][i] = 0.f;

        #pragma unroll
        for (int ks = 0; ks < 2; ks++) {
            uint32_t ah[4], al2[4];
            uint32_t ad = qB + a_row * ASTRIDE + (ks << 5) + a_off;
            LDSM4(ah, ad);
            LDSM4(al2, ad + 64);
            #pragma unroll
            for (int gg = 0; gg < 4; gg++) {
                uint32_t bh4[4], bl4[4];
                uint32_t kd = kC + (gg * 16 + kb_part) * ASTRIDE + (ks << 5) + kb_off;
                LDSM4(bh4, kd);
                LDSM4(bl4, kd + 64);
                #pragma unroll
                for (int sub = 0; sub < 2; sub++) {
                    const int nt = gg * 2 + sub, rs = sub << 1;
                    MMA16816(S[nt], ah, bh4[rs], bh4[rs + 1]);
                    MMA16816(S[nt], ah, bl4[rs], bl4[rs + 1]);
                    MMA16816(S[nt], al2, bh4[rs], bh4[rs + 1]);
                }
            }
        }

        // online softmax (base-2)
        float mt0 = -1e30f, mt1 = -1e30f;
        #pragma unroll
        for (int nt = 0; nt < 8; nt++) {
            #pragma unroll
            for (int i = 0; i < 4; i++) S[nt][i] *= SCALE2;
            mt0 = fmaxf(mt0, fmaxf(S[nt][0], S[nt][1]));
            mt1 = fmaxf(mt1, fmaxf(S[nt][2], S[nt][3]));
        }
        mt0 = fmaxf(mt0, __shfl_xor_sync(0xffffffffu, mt0, 1));
        mt0 = fmaxf(mt0, __shfl_xor_sync(0xffffffffu, mt0, 2));
        mt1 = fmaxf(mt1, __shfl_xor_sync(0xffffffffu, mt1, 1));
        mt1 = fmaxf(mt1, __shfl_xor_sync(0xffffffffu, mt1, 2));
        const float mn0 = fmaxf(m0, mt0), mn1 = fmaxf(m1, mt1);
        const float al0 = ex2f(m0 - mn0), al1 = ex2f(m1 - mn1);
        l0 *= al0; l1 *= al1;
        #pragma unroll
        for (int j = 0; j < 4; j++) {
            O[j][0] *= al0; O[j][1] *= al0; O[j][2] *= al1; O[j][3] *= al1;
        }

        uint32_t ph01[8], ph23[8], pl01[8], pl23[8];
        float rs0 = 0.f, rs1 = 0.f;
        #pragma unroll
        for (int nt = 0; nt < 8; nt++) {
            float p0 = ex2f(S[nt][0] - mn0);
            float p1 = ex2f(S[nt][1] - mn0);
            float p2 = ex2f(S[nt][2] - mn1);
            float p3 = ex2f(S[nt][3] - mn1);
            rs0 += p0 + p1; rs1 += p2 + p3;
            split2(p0, p1, ph01[nt], pl01[nt]);
            split2(p2, p3, ph23[nt], pl23[nt]);
        }
        rs0 += __shfl_xor_sync(0xffffffffu, rs0, 1);
        rs0 += __shfl_xor_sync(0xffffffffu, rs0, 2);
        rs1 += __shfl_xor_sync(0xffffffffu, rs1, 1);
        rs1 += __shfl_xor_sync(0xffffffffu, rs1, 2);
        l0 += rs0; l1 += rs1;
        m0 = mn0; m1 = mn1;

        // O += P V (3-term split)
        #pragma unroll
        for (int s = 0; s < 4; s++) {
            uint32_t pah[4] = {ph01[2*s], ph23[2*s], ph01[2*s+1], ph23[2*s+1]};
            uint32_t pal[4] = {pl01[2*s], pl23[2*s], pl01[2*s+1], pl23[2*s+1]};
            #pragma unroll
            for (int hof = 0; hof < 2; hof++) {
                uint32_t vh4[4], vl4[4];
                uint32_t vd = vC + (s * 16 + v_row) * ASTRIDE + (hof << 5) + v_off;
                LDSM4_T(vh4, vd);
                LDSM4_T(vl4, vd + 64);
                #pragma unroll
                for (int sub = 0; sub < 2; sub++) {
                    const int j = hof * 2 + sub, rs = sub << 1;
                    MMA16816(O[j], pah, vh4[rs], vh4[rs + 1]);
                    MMA16816(O[j], pah, vl4[rs], vl4[rs + 1]);
                    MMA16816(O[j], pal, vh4[rs], vh4[rs + 1]);
                }
            }
        }
        if (more) {
            CP_WAIT0();
            __syncthreads();
            cur ^= 1;
        }
    }

    // epilogue: write split planes
    const float inv0 = 1.f / l0, inv1 = 1.f / l1;
    const int gr = lane >> 2, c2 = (lane & 3) << 1;
    const int row0 = q0 + wm16 + gr;
    const size_t ob = (rowbase + row0) * Dq + h * HDq;
    #pragma unroll
    for (int j = 0; j < 4; j++) {
        const int col = j * 8 + c2;
        uint32_t hh, gg2;
        split2(O[j][0] * inv0, O[j][1] * inv0, hh, gg2);
        *(uint32_t*)&outh[ob + col] = hh;
        *(uint32_t*)&outl[ob + col] = gg2;
        split2(O[j][2] * inv1, O[j][3] * inv1, hh, gg2);
        *(uint32_t*)&outh[ob + 8 * (size_t)Dq + col] = hh;
        *(uint32_t*)&outl[ob + 8 * (size_t)Dq + col] = gg2;
    }
}

// ---------------- per-row LayerNorm: fp32 shortcut + split planes ------------
__device__ __forceinline__ float blk_sum256(float v, float* sh8)
{
    const int t = threadIdx.x;
    #pragma unroll
    for (int o = 16; o > 0; o >>= 1) v += __shfl_xor_sync(0xffffffffu, v, o);
    if ((t & 31) == 0) sh8[t >> 5] = v;
    __syncthreads();
    float r = 0.f;
    #pragma unroll
    for (int i = 0; i < 8; i++) r += sh8[i];
    __syncthreads();
    return r;
}

__global__ void ln_kernel(const float* __restrict__ in, const float* __restrict__ g,
                          const float* __restrict__ be, float* __restrict__ outp,
                          __nv_bfloat16* __restrict__ oh, __nv_bfloat16* __restrict__ ol)
{
    __shared__ float sh8[8];
    const int row = blockIdx.x;
    const int t = threadIdx.x;
    const float v = in[(size_t)row * Dq + t];
    const float mu = blk_sum256(v, sh8) * (1.0f / Dq);
    const float d = v - mu;
    const float var = blk_sum256(d * d, sh8) * (1.0f / Dq);
    const float inv = rsqrtf(var + 1e-5f);
    const float o = d * inv * g[t] + be[t];
    outp[(size_t)row * Dq + t] = o;
    __nv_bfloat16 hb = __float2bfloat16(o);
    oh[(size_t)row * Dq + t] = hb;
    ol[(size_t)row * Dq + t] = __float2bfloat16(o - __bfloat162float(hb));
}

// ---------------- launch ------------------------------------------------------
extern "C" void kernel_launch(void* const* d_in, const int* in_sizes, int n_in,
                              void* d_out, int out_size)
{
    const float* x      = (const float*)d_in[0];
    const float* qkv_w  = (const float*)d_in[1];
    const float* proj_w = (const float*)d_in[2];
    const float* proj_b = (const float*)d_in[3];
    const float* fc1_w  = (const float*)d_in[4];
    const float* fc1_b  = (const float*)d_in[5];
    const float* fc2_w  = (const float*)d_in[6];
    const float* fc2_b  = (const float*)d_in[7];
    const float* ln1_g  = (const float*)d_in[8];
    const float* ln1_b  = (const float*)d_in[9];
    float* out = (float*)d_out;

    __nv_bfloat16 *qwh, *qwl, *pwh, *pwl, *f1h, *f1l, *f2h, *f2l;
    __nv_bfloat16 *qkvh, *qkvl, *atth, *attl, *neth, *netl, *h1h, *h1l;
    float *proj, *net;
    cudaGetSymbolAddress((void**)&qwh, g_qkvwh); cudaGetSymbolAddress((void**)&qwl, g_qkvwl);
    cudaGetSymbolAddress((void**)&pwh, g_projwh);cudaGetSymbolAddress((void**)&pwl, g_projwl);
    cudaGetSymbolAddress((void**)&f1h, g_fc1wh); cudaGetSymbolAddress((void**)&f1l, g_fc1wl);
    cudaGetSymbolAddress((void**)&f2h, g_fc2wh); cudaGetSymbolAddress((void**)&f2l, g_fc2wl);
    cudaGetSymbolAddress((void**)&qkvh, g_qkvh); cudaGetSymbolAddress((void**)&qkvl, g_qkvl);
    cudaGetSymbolAddress((void**)&atth, g_atth); cudaGetSymbolAddress((void**)&attl, g_attl);
    cudaGetSymbolAddress((void**)&neth, g_neth); cudaGetSymbolAddress((void**)&netl, g_netl);
    cudaGetSymbolAddress((void**)&h1h, g_h1h);   cudaGetSymbolAddress((void**)&h1l, g_h1l);
    cudaGetSymbolAddress((void**)&proj, g_proj); cudaGetSymbolAddress((void**)&net, g_net);

    cudaFuncSetAttribute(gemm_p<2,2,1,1>, cudaFuncAttributeMaxDynamicSharedMemorySize, GEMM_SMEM_22);
    cudaFuncSetAttribute(gemm_p<2,2,0,1>, cudaFuncAttributeMaxDynamicSharedMemorySize, GEMM_SMEM_22);
    cudaFuncSetAttribute(gemm_p<1,1,0,0>, cudaFuncAttributeMaxDynamicSharedMemorySize, GEMM_SMEM_11);
    cudaFuncSetAttribute(attn_mma, cudaFuncAttributeMaxDynamicSharedMemorySize, ATTN_SMEM);

    // 0) fused weight prep
    prep_w<<<768, 256>>>(qkv_w, proj_w, fc1_w, fc2_w,
                         qwh, qwl, pwh, pwl, f1h, f1l, f2h, f2l);
    // 1) QKV = X @ Wqkv (128x64 tiles, A fp32 reg-staged) -> planes
    gemm_p<2, 2, 1, 1><<<dim3(768 / 64, ROWS / 128), 256, GEMM_SMEM_22>>>(
        nullptr, nullptr, x, qwh, qwl, nullptr, nullptr,
        nullptr, qkvh, qkvl, ROWS, 768, Dq);
    // 2) attention (128-q CTAs, 256 threads) -> planes
    attn_mma<<<dim3(Nq / 128, Bq * Hq), 256, ATTN_SMEM>>>(qkvh, qkvl, atth, attl);
    // 3) proj + bias + residual (64x32 tiles -> 512 CTAs) -> fp32
    gemm_p<1, 1, 0, 0><<<dim3(Dq / 32, ROWS / 64), 256, GEMM_SMEM_11>>>(
        atth, attl, nullptr, pwh, pwl, proj_b, x,
        proj, nullptr, nullptr, ROWS, Dq, Dq);
    // 4) LayerNorm -> fp32 shortcut + planes
    ln_kernel<<<ROWS, 256>>>(proj, ln1_g, ln1_b, net, neth, netl);
    // 5) fc1 + bias (128x64 tiles) -> planes
    gemm_p<2, 2, 0, 1><<<dim3(DFFq / 64, ROWS / 128), 256, GEMM_SMEM_22>>>(
        neth, netl, nullptr, f1h, f1l, fc1_b, nullptr,
        nullptr, h1h, h1l, ROWS, DFFq, Dq);
    // 6) fc2 + bias + shortcut (64x32 tiles -> 512 CTAs) -> d_out fp32
    gemm_p<1, 1, 0, 0><<<dim3(Dq / 32, ROWS / 64), 256, GEMM_SMEM_11>>>(
        h1h, h1l, nullptr, f2h, f2l, fc2_b, net,
        out, nullptr, nullptr, ROWS, Dq, DFFq);
}

// round 12
// speedup vs baseline: 1.0518x; 1.0518x over previous
#include <cuda_runtime.h>
#include <cuda_bf16.h>
#include <math.h>
#include <stdint.h>

#define Bq 2
#define Nq 2048
#define Dq 256
#define Hq 8
#define HDq 32
#define DFFq 1024
#define ROWS (Bq*Nq)          // 4096
#define KVSPLIT 4
#define KVCHUNK (Nq / KVSPLIT)   // 512

// ---------------- scratch (device globals; no allocs allowed) ----------------
__device__ __nv_bfloat16 g_qkvwh[768 * 256],  g_qkvwl[768 * 256];   // [N,K] planes
__device__ __nv_bfloat16 g_projwh[256 * 256], g_projwl[256 * 256];
__device__ __nv_bfloat16 g_fc1wh[1024 * 256], g_fc1wl[1024 * 256];
__device__ __nv_bfloat16 g_fc2wh[256 * 1024], g_fc2wl[256 * 1024];
__device__ __nv_bfloat16 g_qkvh[ROWS * 768],  g_qkvl[ROWS * 768];
__device__ __nv_bfloat16 g_atth[ROWS * Dq],   g_attl[ROWS * Dq];
__device__ __nv_bfloat16 g_neth[ROWS * Dq],   g_netl[ROWS * Dq];
__device__ __nv_bfloat16 g_h1h[ROWS * DFFq],  g_h1l[ROWS * DFFq];
__device__ float  g_pO[KVSPLIT * ROWS * Dq];       // unnormalized partial O
__device__ float2 g_pml[KVSPLIT * ROWS * Hq];      // partial (m, l)
__device__ float g_proj[ROWS * Dq];   // pre-LN fp32
__device__ float g_net[ROWS * Dq];    // shortcut fp32

// ---------------- helpers ------------------------------------------------------
__device__ __forceinline__ uint32_t smem_u32(const void* p) {
    uint32_t a;
    asm("{ .reg .u64 t; cvta.to.shared.u64 t, %1; cvt.u32.u64 %0, t; }"
        : "=r"(a) : "l"(p));
    return a;
}
__device__ __forceinline__ void cp16(uint32_t dst, const void* src) {
    asm volatile("cp.async.cg.shared.global [%0], [%1], 16;" :: "r"(dst), "l"(src));
}
#define CP_COMMIT() asm volatile("cp.async.commit_group;" ::: "memory")
#define CP_WAIT0()  asm volatile("cp.async.wait_group 0;" ::: "memory")

__device__ __forceinline__ float ex2f(float x) {
    float y; asm("ex2.approx.f32 %0, %1;" : "=f"(y) : "f"(x)); return y;
}
__device__ __forceinline__ void split4(float4 a, uint32_t& h01, uint32_t& h23,
                                       uint32_t& g01, uint32_t& g23) {
    asm("cvt.rn.bf16x2.f32 %0, %1, %2;" : "=r"(h01) : "f"(a.y), "f"(a.x));
    asm("cvt.rn.bf16x2.f32 %0, %1, %2;" : "=r"(h23) : "f"(a.w), "f"(a.z));
    float l0 = a.x - __int_as_float(h01 << 16);
    float l1 = a.y - __int_as_float(h01 & 0xffff0000u);
    float l2 = a.z - __int_as_float(h23 << 16);
    float l3 = a.w - __int_as_float(h23 & 0xffff0000u);
    asm("cvt.rn.bf16x2.f32 %0, %1, %2;" : "=r"(g01) : "f"(l1), "f"(l0));
    asm("cvt.rn.bf16x2.f32 %0, %1, %2;" : "=r"(g23) : "f"(l3), "f"(l2));
}
__device__ __forceinline__ void split2(float a, float b, uint32_t& h, uint32_t& g) {
    asm("cvt.rn.bf16x2.f32 %0, %1, %2;" : "=r"(h) : "f"(b), "f"(a));
    float la = a - __int_as_float(h << 16);
    float lb = b - __int_as_float(h & 0xffff0000u);
    asm("cvt.rn.bf16x2.f32 %0, %1, %2;" : "=r"(g) : "f"(lb), "f"(la));
}

#define LDSM4(r, addr) \
    asm volatile("ldmatrix.sync.aligned.m8n8.x4.shared.b16 {%0,%1,%2,%3}, [%4];" \
        : "=r"((r)[0]), "=r"((r)[1]), "=r"((r)[2]), "=r"((r)[3]) : "r"(addr))
#define LDSM4_T(r, addr) \
    asm volatile("ldmatrix.sync.aligned.m8n8.x4.trans.shared.b16 {%0,%1,%2,%3}, [%4];" \
        : "=r"((r)[0]), "=r"((r)[1]), "=r"((r)[2]), "=r"((r)[3]) : "r"(addr))
#define MMA16816(d, a, b0, b1) \
    asm volatile("mma.sync.aligned.m16n8k16.row.col.f32.bf16.bf16.f32 " \
        "{%0,%1,%2,%3}, {%4,%5,%6,%7}, {%8,%9}, {%0,%1,%2,%3};" \
        : "+f"((d)[0]), "+f"((d)[1]), "+f"((d)[2]), "+f"((d)[3]) \
        : "r"((a)[0]), "r"((a)[1]), "r"((a)[2]), "r"((a)[3]), "r"(b0), "r"(b1))

#define ASTRIDE 144

// ================= fused weight prep: transpose + bf16 hi/lo split ===========
__global__ void __launch_bounds__(256)
prep_w(const float* __restrict__ qkv_w, const float* __restrict__ proj_w,
       const float* __restrict__ fc1_w, const float* __restrict__ fc2_w,
       __nv_bfloat16* __restrict__ qwh, __nv_bfloat16* __restrict__ qwl,
       __nv_bfloat16* __restrict__ pwh, __nv_bfloat16* __restrict__ pwl,
       __nv_bfloat16* __restrict__ f1h, __nv_bfloat16* __restrict__ f1l,
       __nv_bfloat16* __restrict__ f2h, __nv_bfloat16* __restrict__ f2l)
{
    __shared__ float tile[32][33];
    const int bid = blockIdx.x;
    const float* W; __nv_bfloat16 *th, *tl; int K, N, tid;
    if (bid < 192)      { W = qkv_w;  th = qwh; tl = qwl; K = 256;  N = 768;  tid = bid; }
    else if (bid < 256) { W = proj_w; th = pwh; tl = pwl; K = 256;  N = 256;  tid = bid - 192; }
    else if (bid < 512) { W = fc1_w;  th = f1h; tl = f1l; K = 256;  N = 1024; tid = bid - 256; }
    else                { W = fc2_w;  th = f2h; tl = f2l; K = 1024; N = 256;  tid = bid - 512; }
    const int nt = N >> 5;
    const int nb = (tid % nt) << 5, kb = (tid / nt) << 5;
    const int tx = threadIdx.x & 31, ty = threadIdx.x >> 5;   // 32 x 8
    #pragma unroll
    for (int i = 0; i < 4; i++)
        tile[ty + 8 * i][tx] = W[(size_t)(kb + ty + 8 * i) * N + nb + tx];
    __syncthreads();
    #pragma unroll
    for (int i = 0; i < 4; i++) {
        const int n = nb + ty + 8 * i, k = kb + tx;
        float v = tile[tx][ty + 8 * i];
        __nv_bfloat16 h = __float2bfloat16(v);
        th[(size_t)n * K + k] = h;
        tl[(size_t)n * K + k] = __float2bfloat16(v - __bfloat162float(h));
    }
}

// ================= bf16x3-split GEMM, cp.async double-buffered ===============
// C[M,N] = A[M,K]@B^T. CTA tile (MT*64)x(NT*32), BK=32, 256 threads (4m x 2n).
// AMODE 0: A planes (cp.async). AMODE 1: A fp32 reg-staged + split (MT=2 only).
// OUTMODE 0: fp32 C (+bias)(+res). OUTMODE 1: planes Ch/Cl (+bias).
template<int MT, int NT, int AMODE, int OUTMODE>
__global__ void __launch_bounds__(256)
gemm_p(const __nv_bfloat16* __restrict__ Ah, const __nv_bfloat16* __restrict__ Al,
       const float* __restrict__ Af,
       const __nv_bfloat16* __restrict__ Bh, const __nv_bfloat16* __restrict__ Bl,
       const float* __restrict__ bias, const float* __restrict__ res,
       float* __restrict__ C, __nv_bfloat16* __restrict__ Ch,
       __nv_bfloat16* __restrict__ Cl, int M, int N, int K)
{
    constexpr int BM = MT * 64;
    constexpr int BN = NT * 32;
    constexpr int AB = BM * ASTRIDE;
    constexpr int BNB = BN * ASTRIDE;
    extern __shared__ char smem[];
    const uint32_t aB = smem_u32(smem);
    const uint32_t bB = aB + 2 * AB;

    const int t    = threadIdx.x;
    const int wid  = t >> 5, lane = t & 31;
    const int bm   = blockIdx.y * BM;
    const int bn   = blockIdx.x * BN;
    const int wm   = (wid & 3) * (MT * 16);
    const int wn   = (wid >> 2) * (NT * 16);
    const int ar   = t >> 2, asg = t & 3;

    float acc[MT][2 * NT][4];
    #pragma unroll
    for (int i = 0; i < MT; i++)
        #pragma unroll
        for (int j = 0; j < 2 * NT; j++)
            #pragma unroll
            for (int k = 0; k < 4; k++) acc[i][j][k] = 0.f;

    const uint32_t a_row = wm + (lane & 15);
    const uint32_t a_off = (lane >> 4) << 4;
    const uint32_t b_row = wn + (lane & 7) + ((lane >> 4) << 3);
    const uint32_t b_off = ((lane >> 3) & 1) << 4;

    float4 apf[4];

    auto cpA = [&](int buf, int k0) {
        const uint32_t d0 = aB + buf * AB;
        #pragma unroll
        for (int i = 0; i < MT; i++) {
            const int r = ar + i * 64;
            const size_t go = (size_t)(bm + r) * K + k0 + asg * 8;
            uint32_t dst = d0 + r * ASTRIDE + asg * 16;
            cp16(dst, Ah + go);
            cp16(dst + 64, Al + go);
        }
    };
    auto cpB = [&](int buf, int k0) {
        if (NT == 2 || t < 128) {
            const size_t go = (size_t)(bn + ar) * K + k0 + asg * 8;
            uint32_t dst = bB + buf * BNB + ar * ASTRIDE + asg * 16;
            cp16(dst, Bh + go);
            cp16(dst + 64, Bl + go);
        }
    };
    auto ldgA = [&](int k0) {
        #pragma unroll
        for (int i = 0; i < 4; i++) {
            int idx = i * 256 + t;
            int r = idx >> 3, q = (idx & 7) << 2;
            apf[i] = *(const float4*)&Af[(size_t)(bm + r) * K + k0 + q];
        }
    };
    auto stsA = [&](int buf) {
        const uint32_t d0 = aB + buf * AB;
        #pragma unroll
        for (int i = 0; i < 4; i++) {
            int idx = i * 256 + t;
            int r = idx >> 3, q = (idx & 7) << 2;
            uint32_t h01, h23, g01, g23;
            split4(apf[i], h01, h23, g01, g23);
            uint32_t ad = d0 + r * ASTRIDE + (q << 1);
            asm volatile("st.shared.v2.b32 [%0], {%1,%2};" :: "r"(ad), "r"(h01), "r"(h23));
            asm volatile("st.shared.v2.b32 [%0], {%1,%2};" :: "r"(ad + 64), "r"(g01), "r"(g23));
        }
    };

    if (AMODE == 0) cpA(0, 0); else { ldgA(0); stsA(0); }
    cpB(0, 0);
    CP_COMMIT();
    CP_WAIT0();
    __syncthreads();

    const int T = K >> 5;
    int cur = 0;
    for (int i = 0; i < T; i++) {
        const bool more = (i + 1 < T);
        if (more) {
            const int kn = (i + 1) << 5;
            if (AMODE == 0) cpA(cur ^ 1, kn); else ldgA(kn);
            cpB(cur ^ 1, kn);
            CP_COMMIT();
        }
        const uint32_t aC = aB + cur * AB;
        const uint32_t bC = bB + cur * BNB;
        #pragma unroll
        for (int ks = 0; ks < 2; ks++) {
            uint32_t ah[MT][4], al2[MT][4], bh[NT][4], bl[NT][4];
            #pragma unroll
            for (int mt = 0; mt < MT; mt++) {
                uint32_t ad = aC + (a_row + mt * 16) * ASTRIDE + (ks << 5) + a_off;
                LDSM4(ah[mt], ad);
                LDSM4(al2[mt], ad + 64);
            }
            #pragma unroll
            for (int gg = 0; gg < NT; gg++) {
                uint32_t bd = bC + (b_row + gg * 16) * ASTRIDE + (ks << 5) + b_off;
                LDSM4(bh[gg], bd);
                LDSM4(bl[gg], bd + 64);
            }
            #pragma unroll
            for (int mt = 0; mt < MT; mt++)
                #pragma unroll
                for (int nt = 0; nt < 2 * NT; nt++) {
                    const int gsel = nt >> 1, rsel = (nt & 1) << 1;
                    uint32_t bh0 = bh[gsel][rsel], bh1 = bh[gsel][rsel + 1];
                    uint32_t bl0 = bl[gsel][rsel], bl1 = bl[gsel][rsel + 1];
                    MMA16816(acc[mt][nt], ah[mt], bh0, bh1);
                    MMA16816(acc[mt][nt], ah[mt], bl0, bl1);
                    MMA16816(acc[mt][nt], al2[mt], bh0, bh1);
                }
        }
        if (more) {
            if (AMODE == 1) stsA(cur ^ 1);
            CP_WAIT0();
            __syncthreads();
            cur ^= 1;
        }
    }

    const int gr = lane >> 2, c2 = (lane & 3) << 1;
    #pragma unroll
    for (int mt = 0; mt < MT; mt++)
        #pragma unroll
        for (int nt = 0; nt < 2 * NT; nt++) {
            const int row = bm + wm + mt * 16 + gr;
            const int col = bn + wn + nt * 8 + c2;
            float2 v0 = make_float2(acc[mt][nt][0], acc[mt][nt][1]);
            float2 v1 = make_float2(acc[mt][nt][2], acc[mt][nt][3]);
            if (bias) {
                float2 bb = *(const float2*)&bias[col];
                v0.x += bb.x; v0.y += bb.y; v1.x += bb.x; v1.y += bb.y;
            }
            if (OUTMODE == 0) {
                if (res) {
                    float2 r0 = *(const float2*)&res[(size_t)row * N + col];
                    float2 r1 = *(const float2*)&res[(size_t)(row + 8) * N + col];
                    v0.x += r0.x; v0.y += r0.y; v1.x += r1.x; v1.y += r1.y;
                }
                *(float2*)&C[(size_t)row * N + col] = v0;
                *(float2*)&C[(size_t)(row + 8) * N + col] = v1;
            } else {
                uint32_t h, g;
                split2(v0.x, v0.y, h, g);
                *(uint32_t*)&Ch[(size_t)row * N + col] = h;
                *(uint32_t*)&Cl[(size_t)row * N + col] = g;
                split2(v1.x, v1.y, h, g);
                *(uint32_t*)&Ch[(size_t)(row + 8) * N + col] = h;
                *(uint32_t*)&Cl[(size_t)(row + 8) * N + col] = g;
            }
        }
}
#define GEMM_SMEM_22 (2 * (128 * ASTRIDE) + 2 * (64 * ASTRIDE))   // 55296
#define GEMM_SMEM_12 (2 * (64 * ASTRIDE) + 2 * (64 * ASTRIDE))    // 36864

// ================= tensor-core flash attention, split-KV ======================
// grid (Nq/128, B*H, KVSPLIT), 256 threads = 8 warps x m16. KV tiles of 64 keys.
// Each z-CTA handles KVCHUNK keys, emits unnormalized partial O + (m, l).
#define SCALE2 (5.656854249492381f * 1.4426950408889634f)
#define ABYTES128 (128 * ASTRIDE)
#define KVBYTES (64 * ASTRIDE)
#define ATTN_SMEM (ABYTES128 + 4 * KVBYTES)       // 55296
__global__ void __launch_bounds__(256)
attn_mma(const __nv_bfloat16* __restrict__ qkvh,
         const __nv_bfloat16* __restrict__ qkvl,
         float* __restrict__ pO, float2* __restrict__ pml)
{
    extern __shared__ char smem[];
    const uint32_t qB = smem_u32(smem);
    const uint32_t kB0 = qB + ABYTES128;
    const uint32_t vB0 = kB0 + 2 * KVBYTES;

    const int t = threadIdx.x, wid = t >> 5, lane = t & 31;
    const int q0 = blockIdx.x * 128;
    const int bh = blockIdx.y;
    const int kz = blockIdx.z;
    const int kbase = kz * KVCHUNK;
    const int b = bh >> 3, h = bh & 7;
    const size_t rowbase = (size_t)b * Nq;
    const __nv_bfloat16* qh = qkvh + rowbase * 768 + h * HDq;
    const __nv_bfloat16* ql = qkvl + rowbase * 768 + h * HDq;

    const int ar = t >> 2, asg = t & 3;

    auto cpKV = [&](int kt, int buf) {
        const size_t go = (size_t)(kt + ar) * 768 + asg * 8;
        uint32_t kd = kB0 + buf * KVBYTES + ar * ASTRIDE + asg * 16;
        cp16(kd,      qh + go + 256);
        cp16(kd + 64, ql + go + 256);
        uint32_t vd = vB0 + buf * KVBYTES + ar * ASTRIDE + asg * 16;
        cp16(vd,      qh + go + 512);
        cp16(vd + 64, ql + go + 512);
    };

    // Q tile: 128 x 32, both planes
    #pragma unroll
    for (int i = 0; i < 2; i++) {
        const int r = ar + i * 64;
        const size_t go = (size_t)(q0 + r) * 768 + asg * 8;
        uint32_t dst = qB + r * ASTRIDE + asg * 16;
        cp16(dst, qh + go);
        cp16(dst + 64, ql + go);
    }
    cpKV(kbase, 0);
    CP_COMMIT();

    const int wm16 = wid * 16;
    const uint32_t a_row = wm16 + (lane & 15);
    const uint32_t a_off = (lane >> 4) << 4;
    const uint32_t kb_part = (lane & 7) + ((lane >> 4) << 3);
    const uint32_t kb_off  = ((lane >> 3) & 1) << 4;
    const uint32_t v_row = (lane & 7) + (((lane >> 3) & 1) << 3);
    const uint32_t v_off = (lane >> 4) << 4;

    float m0 = -1e30f, m1 = -1e30f, l0 = 0.f, l1 = 0.f;
    float O[4][4];
    #pragma unroll
    for (int j = 0; j < 4; j++)
        #pragma unroll
        for (int i = 0; i < 4; i++) O[j][i] = 0.f;

    CP_WAIT0();
    __syncthreads();

    int cur = 0;
    for (int kt = kbase; kt < kbase + KVCHUNK; kt += 64) {
        const bool more = (kt + 64 < kbase + KVCHUNK);
        if (more) { cpKV(kt + 64, cur ^ 1); CP_COMMIT(); }

        const uint32_t kC = kB0 + cur * KVBYTES;
        const uint32_t vC = vB0 + cur * KVBYTES;

        // S = Q K^T (3-term split)
        float S[8][4];
        #pragma unroll
        for (int nt = 0; nt < 8; nt++)
            #pragma unroll
            for (int i = 0; i < 4; i++) S[nt][i] = 0.f;

        #pragma unroll
        for (int ks = 0; ks < 2; ks++) {
            uint32_t ah[4], al2[4];
            uint32_t ad = qB + a_row * ASTRIDE + (ks << 5) + a_off;
            LDSM4(ah, ad);
            LDSM4(al2, ad + 64);
            #pragma unroll
            for (int gg = 0; gg < 4; gg++) {
                uint32_t bh4[4], bl4[4];
                uint32_t kd = kC + (gg * 16 + kb_part) * ASTRIDE + (ks << 5) + kb_off;
                LDSM4(bh4, kd);
                LDSM4(bl4, kd + 64);
                #pragma unroll
                for (int sub = 0; sub < 2; sub++) {
                    const int nt = gg * 2 + sub, rs = sub << 1;
                    MMA16816(S[nt], ah, bh4[rs], bh4[rs + 1]);
                    MMA16816(S[nt], ah, bl4[rs], bl4[rs + 1]);
                    MMA16816(S[nt], al2, bh4[rs], bh4[rs + 1]);
                }
            }
        }

        // online softmax (base-2)
        float mt0 = -1e30f, mt1 = -1e30f;
        #pragma unroll
        for (int nt = 0; nt < 8; nt++) {
            #pragma unroll
            for (int i = 0; i < 4; i++) S[nt][i] *= SCALE2;
            mt0 = fmaxf(mt0, fmaxf(S[nt][0], S[nt][1]));
            mt1 = fmaxf(mt1, fmaxf(S[nt][2], S[nt][3]));
        }
        mt0 = fmaxf(mt0, __shfl_xor_sync(0xffffffffu, mt0, 1));
        mt0 = fmaxf(mt0, __shfl_xor_sync(0xffffffffu, mt0, 2));
        mt1 = fmaxf(mt1, __shfl_xor_sync(0xffffffffu, mt1, 1));
        mt1 = fmaxf(mt1, __shfl_xor_sync(0xffffffffu, mt1, 2));
        const float mn0 = fmaxf(m0, mt0), mn1 = fmaxf(m1, mt1);
        const float al0 = ex2f(m0 - mn0), al1 = ex2f(m1 - mn1);
        l0 *= al0; l1 *= al1;
        #pragma unroll
        for (int j = 0; j < 4; j++) {
            O[j][0] *= al0; O[j][1] *= al0; O[j][2] *= al1; O[j][3] *= al1;
        }

        uint32_t ph01[8], ph23[8], pl01[8], pl23[8];
        float rs0 = 0.f, rs1 = 0.f;
        #pragma unroll
        for (int nt = 0; nt < 8; nt++) {
            float p0 = ex2f(S[nt][0] - mn0);
            float p1 = ex2f(S[nt][1] - mn0);
            float p2 = ex2f(S[nt][2] - mn1);
            float p3 = ex2f(S[nt][3] - mn1);
            rs0 += p0 + p1; rs1 += p2 + p3;
            split2(p0, p1, ph01[nt], pl01[nt]);
            split2(p2, p3, ph23[nt], pl23[nt]);
        }
        rs0 += __shfl_xor_sync(0xffffffffu, rs0, 1);
        rs0 += __shfl_xor_sync(0xffffffffu, rs0, 2);
        rs1 += __shfl_xor_sync(0xffffffffu, rs1, 1);
        rs1 += __shfl_xor_sync(0xffffffffu, rs1, 2);
        l0 += rs0; l1 += rs1;
        m0 = mn0; m1 = mn1;

        // O += P V (3-term split)
        #pragma unroll
        for (int s = 0; s < 4; s++) {
            uint32_t pah[4] = {ph01[2*s], ph23[2*s], ph01[2*s+1], ph23[2*s+1]};
            uint32_t pal[4] = {pl01[2*s], pl23[2*s], pl01[2*s+1], pl23[2*s+1]};
            #pragma unroll
            for (int hof = 0; hof < 2; hof++) {
                uint32_t vh4[4], vl4[4];
                uint32_t vd = vC + (s * 16 + v_row) * ASTRIDE + (hof << 5) + v_off;
                LDSM4_T(vh4, vd);
                LDSM4_T(vl4, vd + 64);
                #pragma unroll
                for (int sub = 0; sub < 2; sub++) {
                    const int j = hof * 2 + sub, rs = sub << 1;
                    MMA16816(O[j], pah, vh4[rs], vh4[rs + 1]);
                    MMA16816(O[j], pah, vl4[rs], vl4[rs + 1]);
                    MMA16816(O[j], pal, vh4[rs], vh4[rs + 1]);
                }
            }
        }
        if (more) {
            CP_WAIT0();
            __syncthreads();
            cur ^= 1;
        }
    }

    // epilogue: write UNNORMALIZED partial O (fp32) + (m, l)
    const int gr = lane >> 2, c2 = (lane & 3) << 1;
    const int row0 = q0 + wm16 + gr;
    const size_t ob = ((size_t)kz * ROWS + rowbase + row0) * Dq + h * HDq;
    #pragma unroll
    for (int j = 0; j < 4; j++) {
        const int col = j * 8 + c2;
        *(float2*)&pO[ob + col] = make_float2(O[j][0], O[j][1]);
        *(float2*)&pO[ob + 8 * (size_t)Dq + col] = make_float2(O[j][2], O[j][3]);
    }
    if ((lane & 3) == 0) {
        const size_t mi = (size_t)kz * ROWS * Hq + (rowbase + row0) * Hq + h;
        pml[mi] = make_float2(m0, l0);
        pml[mi + 8 * Hq] = make_float2(m1, l1);
    }
}

// ================= split-KV combine: 4 partials -> split planes ===============
// grid ROWS, 128 threads; thread t handles cols 2t, 2t+1 of its row.
__global__ void __launch_bounds__(128)
attn_combine(const float* __restrict__ pO, const float2* __restrict__ pml,
             __nv_bfloat16* __restrict__ outh, __nv_bfloat16* __restrict__ outl)
{
    const int row = blockIdx.x;
    const int t = threadIdx.x;
    const int c = t << 1;
    const int h = c >> 5;

    float2 ml[KVSPLIT];
    #pragma unroll
    for (int z = 0; z < KVSPLIT; z++)
        ml[z] = pml[(size_t)z * ROWS * Hq + (size_t)row * Hq + h];
    float M = ml[0].x;
    #pragma unroll
    for (int z = 1; z < KVSPLIT; z++) M = fmaxf(M, ml[z].x);
    float L = 0.f, ox = 0.f, oy = 0.f;
    #pragma unroll
    for (int z = 0; z < KVSPLIT; z++) {
        const float w = ex2f(ml[z].x - M);
        L += ml[z].y * w;
        float2 o = *(const float2*)&pO[((size_t)z * ROWS + row) * Dq + c];
        ox += o.x * w; oy += o.y * w;
    }
    const float inv = 1.f / L;
    uint32_t hh, gg;
    split2(ox * inv, oy * inv, hh, gg);
    *(uint32_t*)&outh[(size_t)row * Dq + c] = hh;
    *(uint32_t*)&outl[(size_t)row * Dq + c] = gg;
}

// ---------------- per-row LayerNorm: fp32 shortcut + split planes ------------
__device__ __forceinline__ float blk_sum256(float v, float* sh8)
{
    const int t = threadIdx.x;
    #pragma unroll
    for (int o = 16; o > 0; o >>= 1) v += __shfl_xor_sync(0xffffffffu, v, o);
    if ((t & 31) == 0) sh8[t >> 5] = v;
    __syncthreads();
    float r = 0.f;
    #pragma unroll
    for (int i = 0; i < 8; i++) r += sh8[i];
    __syncthreads();
    return r;
}

__global__ void ln_kernel(const float* __restrict__ in, const float* __restrict__ g,
                          const float* __restrict__ be, float* __restrict__ outp,
                          __nv_bfloat16* __restrict__ oh, __nv_bfloat16* __restrict__ ol)
{
    __shared__ float sh8[8];
    const int row = blockIdx.x;
    const int t = threadIdx.x;
    const float v = in[(size_t)row * Dq + t];
    const float mu = blk_sum256(v, sh8) * (1.0f / Dq);
    const float d = v - mu;
    const float var = blk_sum256(d * d, sh8) * (1.0f / Dq);
    const float inv = rsqrtf(var + 1e-5f);
    const float o = d * inv * g[t] + be[t];
    outp[(size_t)row * Dq + t] = o;
    __nv_bfloat16 hb = __float2bfloat16(o);
    oh[(size_t)row * Dq + t] = hb;
    ol[(size_t)row * Dq + t] = __float2bfloat16(o - __bfloat162float(hb));
}

// ---------------- launch ------------------------------------------------------
extern "C" void kernel_launch(void* const* d_in, const int* in_sizes, int n_in,
                              void* d_out, int out_size)
{
    const float* x      = (const float*)d_in[0];
    const float* qkv_w  = (const float*)d_in[1];
    const float* proj_w = (const float*)d_in[2];
    const float* proj_b = (const float*)d_in[3];
    const float* fc1_w  = (const float*)d_in[4];
    const float* fc1_b  = (const float*)d_in[5];
    const float* fc2_w  = (const float*)d_in[6];
    const float* fc2_b  = (const float*)d_in[7];
    const float* ln1_g  = (const float*)d_in[8];
    const float* ln1_b  = (const float*)d_in[9];
    float* out = (float*)d_out;

    __nv_bfloat16 *qwh, *qwl, *pwh, *pwl, *f1h, *f1l, *f2h, *f2l;
    __nv_bfloat16 *qkvh, *qkvl, *atth, *attl, *neth, *netl, *h1h, *h1l;
    float *proj, *net, *pO; float2* pml;
    cudaGetSymbolAddress((void**)&qwh, g_qkvwh); cudaGetSymbolAddress((void**)&qwl, g_qkvwl);
    cudaGetSymbolAddress((void**)&pwh, g_projwh);cudaGetSymbolAddress((void**)&pwl, g_projwl);
    cudaGetSymbolAddress((void**)&f1h, g_fc1wh); cudaGetSymbolAddress((void**)&f1l, g_fc1wl);
    cudaGetSymbolAddress((void**)&f2h, g_fc2wh); cudaGetSymbolAddress((void**)&f2l, g_fc2wl);
    cudaGetSymbolAddress((void**)&qkvh, g_qkvh); cudaGetSymbolAddress((void**)&qkvl, g_qkvl);
    cudaGetSymbolAddress((void**)&atth, g_atth); cudaGetSymbolAddress((void**)&attl, g_attl);
    cudaGetSymbolAddress((void**)&neth, g_neth); cudaGetSymbolAddress((void**)&netl, g_netl);
    cudaGetSymbolAddress((void**)&h1h, g_h1h);   cudaGetSymbolAddress((void**)&h1l, g_h1l);
    cudaGetSymbolAddress((void**)&proj, g_proj); cudaGetSymbolAddress((void**)&net, g_net);
    cudaGetSymbolAddress((void**)&pO, g_pO);     cudaGetSymbolAddress((void**)&pml, g_pml);

    cudaFuncSetAttribute(gemm_p<2,2,1,1>, cudaFuncAttributeMaxDynamicSharedMemorySize, GEMM_SMEM_22);
    cudaFuncSetAttribute(gemm_p<2,2,0,1>, cudaFuncAttributeMaxDynamicSharedMemorySize, GEMM_SMEM_22);
    cudaFuncSetAttribute(gemm_p<1,2,0,0>, cudaFuncAttributeMaxDynamicSharedMemorySize, GEMM_SMEM_12);
    cudaFuncSetAttribute(attn_mma, cudaFuncAttributeMaxDynamicSharedMemorySize, ATTN_SMEM);

    // 0) fused weight prep
    prep_w<<<768, 256>>>(qkv_w, proj_w, fc1_w, fc2_w,
                         qwh, qwl, pwh, pwl, f1h, f1l, f2h, f2l);
    // 1) QKV = X @ Wqkv (128x64 tiles, A fp32 reg-staged) -> planes
    gemm_p<2, 2, 1, 1><<<dim3(768 / 64, ROWS / 128), 256, GEMM_SMEM_22>>>(
        nullptr, nullptr, x, qwh, qwl, nullptr, nullptr,
        nullptr, qkvh, qkvl, ROWS, 768, Dq);
    // 2) attention split-KV: grid (16, 16, 4) -> partials
    attn_mma<<<dim3(Nq / 128, Bq * Hq, KVSPLIT), 256, ATTN_SMEM>>>(qkvh, qkvl, pO, pml);
    // 2b) combine partials -> planes
    attn_combine<<<ROWS, 128>>>(pO, pml, atth, attl);
    // 3) proj + bias + residual (R10 config: 64x64 tiles, 256 CTAs) -> fp32
    gemm_p<1, 2, 0, 0><<<dim3(Dq / 64, ROWS / 64), 256, GEMM_SMEM_12>>>(
        atth, attl, nullptr, pwh, pwl, proj_b, x,
        proj, nullptr, nullptr, ROWS, Dq, Dq);
    // 4) LayerNorm -> fp32 shortcut + planes
    ln_kernel<<<ROWS, 256>>>(proj, ln1_g, ln1_b, net, neth, netl);
    // 5) fc1 + bias (128x64 tiles) -> planes
    gemm_p<2, 2, 0, 1><<<dim3(DFFq / 64, ROWS / 128), 256, GEMM_SMEM_22>>>(
        neth, netl, nullptr, f1h, f1l, fc1_b, nullptr,
        nullptr, h1h, h1l, ROWS, DFFq, Dq);
    // 6) fc2 + bias + shortcut (R10 config) -> d_out fp32
    gemm_p<1, 2, 0, 0><<<dim3(Dq / 64, ROWS / 64), 256, GEMM_SMEM_12>>>(
        h1h, h1l, nullptr, f2h, f2l, fc2_b, net,
        out, nullptr, nullptr, ROWS, Dq, DFFq);
}

// round 13
// speedup vs baseline: 1.0625x; 1.0101x over previous
#include <cuda_runtime.h>
#include <cuda_bf16.h>
#include <math.h>
#include <stdint.h>

#define Bq 2
#define Nq 2048
#define Dq 256
#define Hq 8
#define HDq 32
#define DFFq 1024
#define ROWS (Bq*Nq)          // 4096
#define KVSPLIT 4
#define KVCHUNK (Nq / KVSPLIT)   // 512

// ---------------- scratch (device globals; no allocs allowed) ----------------
__device__ __nv_bfloat16 g_qkvwh[768 * 256],  g_qkvwl[768 * 256];   // [N,K] planes
__device__ __nv_bfloat16 g_projwh[256 * 256], g_projwl[256 * 256];
__device__ __nv_bfloat16 g_fc1wh[1024 * 256], g_fc1wl[1024 * 256];
__device__ __nv_bfloat16 g_fc2wh[256 * 1024], g_fc2wl[256 * 1024];
__device__ __nv_bfloat16 g_qkvh[ROWS * 768],  g_qkvl[ROWS * 768];
__device__ __nv_bfloat16 g_atth[ROWS * Dq],   g_attl[ROWS * Dq];
__device__ __nv_bfloat16 g_neth[ROWS * Dq],   g_netl[ROWS * Dq];
__device__ __nv_bfloat16 g_h1h[ROWS * DFFq],  g_h1l[ROWS * DFFq];
__device__ float  g_pO[KVSPLIT * ROWS * Dq];       // unnormalized partial O
__device__ float2 g_pml[KVSPLIT * ROWS * Hq];      // partial (m, l)
__device__ float g_proj[ROWS * Dq];   // pre-LN fp32
__device__ float g_net[ROWS * Dq];    // shortcut fp32

// ---------------- helpers ------------------------------------------------------
__device__ __forceinline__ uint32_t smem_u32(const void* p) {
    uint32_t a;
    asm("{ .reg .u64 t; cvta.to.shared.u64 t, %1; cvt.u32.u64 %0, t; }"
        : "=r"(a) : "l"(p));
    return a;
}
__device__ __forceinline__ void cp16(uint32_t dst, const void* src) {
    asm volatile("cp.async.cg.shared.global [%0], [%1], 16;" :: "r"(dst), "l"(src));
}
#define CP_COMMIT() asm volatile("cp.async.commit_group;" ::: "memory")
#define CP_WAIT0()  asm volatile("cp.async.wait_group 0;" ::: "memory")

__device__ __forceinline__ float ex2f(float x) {
    float y; asm("ex2.approx.f32 %0, %1;" : "=f"(y) : "f"(x)); return y;
}
__device__ __forceinline__ void split4(float4 a, uint32_t& h01, uint32_t& h23,
                                       uint32_t& g01, uint32_t& g23) {
    asm("cvt.rn.bf16x2.f32 %0, %1, %2;" : "=r"(h01) : "f"(a.y), "f"(a.x));
    asm("cvt.rn.bf16x2.f32 %0, %1, %2;" : "=r"(h23) : "f"(a.w), "f"(a.z));
    float l0 = a.x - __int_as_float(h01 << 16);
    float l1 = a.y - __int_as_float(h01 & 0xffff0000u);
    float l2 = a.z - __int_as_float(h23 << 16);
    float l3 = a.w - __int_as_float(h23 & 0xffff0000u);
    asm("cvt.rn.bf16x2.f32 %0, %1, %2;" : "=r"(g01) : "f"(l1), "f"(l0));
    asm("cvt.rn.bf16x2.f32 %0, %1, %2;" : "=r"(g23) : "f"(l3), "f"(l2));
}
__device__ __forceinline__ void split2(float a, float b, uint32_t& h, uint32_t& g) {
    asm("cvt.rn.bf16x2.f32 %0, %1, %2;" : "=r"(h) : "f"(b), "f"(a));
    float la = a - __int_as_float(h << 16);
    float lb = b - __int_as_float(h & 0xffff0000u);
    asm("cvt.rn.bf16x2.f32 %0, %1, %2;" : "=r"(g) : "f"(lb), "f"(la));
}

#define LDSM4(r, addr) \
    asm volatile("ldmatrix.sync.aligned.m8n8.x4.shared.b16 {%0,%1,%2,%3}, [%4];" \
        : "=r"((r)[0]), "=r"((r)[1]), "=r"((r)[2]), "=r"((r)[3]) : "r"(addr))
#define LDSM4_T(r, addr) \
    asm volatile("ldmatrix.sync.aligned.m8n8.x4.trans.shared.b16 {%0,%1,%2,%3}, [%4];" \
        : "=r"((r)[0]), "=r"((r)[1]), "=r"((r)[2]), "=r"((r)[3]) : "r"(addr))
#define MMA16816(d, a, b0, b1) \
    asm volatile("mma.sync.aligned.m16n8k16.row.col.f32.bf16.bf16.f32 " \
        "{%0,%1,%2,%3}, {%4,%5,%6,%7}, {%8,%9}, {%0,%1,%2,%3};" \
        : "+f"((d)[0]), "+f"((d)[1]), "+f"((d)[2]), "+f"((d)[3]) \
        : "r"((a)[0]), "r"((a)[1]), "r"((a)[2]), "r"((a)[3]), "r"(b0), "r"(b1))

#define ASTRIDE 144

// ================= fused weight prep: transpose + bf16 hi/lo split ===========
__global__ void __launch_bounds__(256)
prep_w(const float* __restrict__ qkv_w, const float* __restrict__ proj_w,
       const float* __restrict__ fc1_w, const float* __restrict__ fc2_w,
       __nv_bfloat16* __restrict__ qwh, __nv_bfloat16* __restrict__ qwl,
       __nv_bfloat16* __restrict__ pwh, __nv_bfloat16* __restrict__ pwl,
       __nv_bfloat16* __restrict__ f1h, __nv_bfloat16* __restrict__ f1l,
       __nv_bfloat16* __restrict__ f2h, __nv_bfloat16* __restrict__ f2l)
{
    __shared__ float tile[32][33];
    const int bid = blockIdx.x;
    const float* W; __nv_bfloat16 *th, *tl; int K, N, tid;
    if (bid < 192)      { W = qkv_w;  th = qwh; tl = qwl; K = 256;  N = 768;  tid = bid; }
    else if (bid < 256) { W = proj_w; th = pwh; tl = pwl; K = 256;  N = 256;  tid = bid - 192; }
    else if (bid < 512) { W = fc1_w;  th = f1h; tl = f1l; K = 256;  N = 1024; tid = bid - 256; }
    else                { W = fc2_w;  th = f2h; tl = f2l; K = 1024; N = 256;  tid = bid - 512; }
    const int nt = N >> 5;
    const int nb = (tid % nt) << 5, kb = (tid / nt) << 5;
    const int tx = threadIdx.x & 31, ty = threadIdx.x >> 5;   // 32 x 8
    #pragma unroll
    for (int i = 0; i < 4; i++)
        tile[ty + 8 * i][tx] = W[(size_t)(kb + ty + 8 * i) * N + nb + tx];
    __syncthreads();
    #pragma unroll
    for (int i = 0; i < 4; i++) {
        const int n = nb + ty + 8 * i, k = kb + tx;
        float v = tile[tx][ty + 8 * i];
        __nv_bfloat16 h = __float2bfloat16(v);
        th[(size_t)n * K + k] = h;
        tl[(size_t)n * K + k] = __float2bfloat16(v - __bfloat162float(h));
    }
}

// ================= bf16x3-split GEMM, cp.async double-buffered ===============
// C[M,N] = A[M,K]@B^T. CTA tile (MT*64)x(NT*32), BK=32, 256 threads (4m x 2n).
// AMODE 0: A planes (cp.async). AMODE 1: A fp32 reg-staged + split (MT=2 only).
// OUTMODE 0: fp32 C (+bias)(+res). OUTMODE 1: planes Ch/Cl (+bias).
template<int MT, int NT, int AMODE, int OUTMODE>
__global__ void __launch_bounds__(256)
gemm_p(const __nv_bfloat16* __restrict__ Ah, const __nv_bfloat16* __restrict__ Al,
       const float* __restrict__ Af,
       const __nv_bfloat16* __restrict__ Bh, const __nv_bfloat16* __restrict__ Bl,
       const float* __restrict__ bias, const float* __restrict__ res,
       float* __restrict__ C, __nv_bfloat16* __restrict__ Ch,
       __nv_bfloat16* __restrict__ Cl, int M, int N, int K)
{
    constexpr int BM = MT * 64;
    constexpr int BN = NT * 32;
    constexpr int AB = BM * ASTRIDE;
    constexpr int BNB = BN * ASTRIDE;
    extern __shared__ char smem[];
    const uint32_t aB = smem_u32(smem);
    const uint32_t bB = aB + 2 * AB;

    const int t    = threadIdx.x;
    const int wid  = t >> 5, lane = t & 31;
    const int bm   = blockIdx.y * BM;
    const int bn   = blockIdx.x * BN;
    const int wm   = (wid & 3) * (MT * 16);
    const int wn   = (wid >> 2) * (NT * 16);
    const int ar   = t >> 2, asg = t & 3;

    float acc[MT][2 * NT][4];
    #pragma unroll
    for (int i = 0; i < MT; i++)
        #pragma unroll
        for (int j = 0; j < 2 * NT; j++)
            #pragma unroll
            for (int k = 0; k < 4; k++) acc[i][j][k] = 0.f;

    const uint32_t a_row = wm + (lane & 15);
    const uint32_t a_off = (lane >> 4) << 4;
    const uint32_t b_row = wn + (lane & 7) + ((lane >> 4) << 3);
    const uint32_t b_off = ((lane >> 3) & 1) << 4;

    float4 apf[4];

    auto cpA = [&](int buf, int k0) {
        const uint32_t d0 = aB + buf * AB;
        #pragma unroll
        for (int i = 0; i < MT; i++) {
            const int r = ar + i * 64;
            const size_t go = (size_t)(bm + r) * K + k0 + asg * 8;
            uint32_t dst = d0 + r * ASTRIDE + asg * 16;
            cp16(dst, Ah + go);
            cp16(dst + 64, Al + go);
        }
    };
    auto cpB = [&](int buf, int k0) {
        if (NT == 2 || t < 128) {
            const size_t go = (size_t)(bn + ar) * K + k0 + asg * 8;
            uint32_t dst = bB + buf * BNB + ar * ASTRIDE + asg * 16;
            cp16(dst, Bh + go);
            cp16(dst + 64, Bl + go);
        }
    };
    auto ldgA = [&](int k0) {
        #pragma unroll
        for (int i = 0; i < 4; i++) {
            int idx = i * 256 + t;
            int r = idx >> 3, q = (idx & 7) << 2;
            apf[i] = *(const float4*)&Af[(size_t)(bm + r) * K + k0 + q];
        }
    };
    auto stsA = [&](int buf) {
        const uint32_t d0 = aB + buf * AB;
        #pragma unroll
        for (int i = 0; i < 4; i++) {
            int idx = i * 256 + t;
            int r = idx >> 3, q = (idx & 7) << 2;
            uint32_t h01, h23, g01, g23;
            split4(apf[i], h01, h23, g01, g23);
            uint32_t ad = d0 + r * ASTRIDE + (q << 1);
            asm volatile("st.shared.v2.b32 [%0], {%1,%2};" :: "r"(ad), "r"(h01), "r"(h23));
            asm volatile("st.shared.v2.b32 [%0], {%1,%2};" :: "r"(ad + 64), "r"(g01), "r"(g23));
        }
    };

    if (AMODE == 0) cpA(0, 0); else { ldgA(0); stsA(0); }
    cpB(0, 0);
    CP_COMMIT();
    CP_WAIT0();
    __syncthreads();

    const int T = K >> 5;
    int cur = 0;
    for (int i = 0; i < T; i++) {
        const bool more = (i + 1 < T);
        if (more) {
            const int kn = (i + 1) << 5;
            if (AMODE == 0) cpA(cur ^ 1, kn); else ldgA(kn);
            cpB(cur ^ 1, kn);
            CP_COMMIT();
        }
        const uint32_t aC = aB + cur * AB;
        const uint32_t bC = bB + cur * BNB;
        #pragma unroll
        for (int ks = 0; ks < 2; ks++) {
            uint32_t ah[MT][4], al2[MT][4], bh[NT][4], bl[NT][4];
            #pragma unroll
            for (int mt = 0; mt < MT; mt++) {
                uint32_t ad = aC + (a_row + mt * 16) * ASTRIDE + (ks << 5) + a_off;
                LDSM4(ah[mt], ad);
                LDSM4(al2[mt], ad + 64);
            }
            #pragma unroll
            for (int gg = 0; gg < NT; gg++) {
                uint32_t bd = bC + (b_row + gg * 16) * ASTRIDE + (ks << 5) + b_off;
                LDSM4(bh[gg], bd);
                LDSM4(bl[gg], bd + 64);
            }
            #pragma unroll
            for (int mt = 0; mt < MT; mt++)
                #pragma unroll
                for (int nt = 0; nt < 2 * NT; nt++) {
                    const int gsel = nt >> 1, rsel = (nt & 1) << 1;
                    uint32_t bh0 = bh[gsel][rsel], bh1 = bh[gsel][rsel + 1];
                    uint32_t bl0 = bl[gsel][rsel], bl1 = bl[gsel][rsel + 1];
                    MMA16816(acc[mt][nt], ah[mt], bh0, bh1);
                    MMA16816(acc[mt][nt], ah[mt], bl0, bl1);
                    MMA16816(acc[mt][nt], al2[mt], bh0, bh1);
                }
        }
        if (more) {
            if (AMODE == 1) stsA(cur ^ 1);
            CP_WAIT0();
            __syncthreads();
            cur ^= 1;
        }
    }

    const int gr = lane >> 2, c2 = (lane & 3) << 1;
    #pragma unroll
    for (int mt = 0; mt < MT; mt++)
        #pragma unroll
        for (int nt = 0; nt < 2 * NT; nt++) {
            const int row = bm + wm + mt * 16 + gr;
            const int col = bn + wn + nt * 8 + c2;
            float2 v0 = make_float2(acc[mt][nt][0], acc[mt][nt][1]);
            float2 v1 = make_float2(acc[mt][nt][2], acc[mt][nt][3]);
            if (bias) {
                float2 bb = *(const float2*)&bias[col];
                v0.x += bb.x; v0.y += bb.y; v1.x += bb.x; v1.y += bb.y;
            }
            if (OUTMODE == 0) {
                if (res) {
                    float2 r0 = *(const float2*)&res[(size_t)row * N + col];
                    float2 r1 = *(const float2*)&res[(size_t)(row + 8) * N + col];
                    v0.x += r0.x; v0.y += r0.y; v1.x += r1.x; v1.y += r1.y;
                }
                *(float2*)&C[(size_t)row * N + col] = v0;
                *(float2*)&C[(size_t)(row + 8) * N + col] = v1;
            } else {
                uint32_t h, g;
                split2(v0.x, v0.y, h, g);
                *(uint32_t*)&Ch[(size_t)row * N + col] = h;
                *(uint32_t*)&Cl[(size_t)row * N + col] = g;
                split2(v1.x, v1.y, h, g);
                *(uint32_t*)&Ch[(size_t)(row + 8) * N + col] = h;
                *(uint32_t*)&Cl[(size_t)(row + 8) * N + col] = g;
            }
        }
}
#define GEMM_SMEM_22 (2 * (128 * ASTRIDE) + 2 * (64 * ASTRIDE))   // 55296
#define GEMM_SMEM_12 (2 * (64 * ASTRIDE) + 2 * (64 * ASTRIDE))    // 36864

// ================= tensor-core flash attention, split-KV ======================
#define SCALE2 (5.656854249492381f * 1.4426950408889634f)
#define ABYTES128 (128 * ASTRIDE)
#define KVBYTES (64 * ASTRIDE)
#define ATTN_SMEM (ABYTES128 + 4 * KVBYTES)       // 55296
__global__ void __launch_bounds__(256)
attn_mma(const __nv_bfloat16* __restrict__ qkvh,
         const __nv_bfloat16* __restrict__ qkvl,
         float* __restrict__ pO, float2* __restrict__ pml)
{
    extern __shared__ char smem[];
    const uint32_t qB = smem_u32(smem);
    const uint32_t kB0 = qB + ABYTES128;
    const uint32_t vB0 = kB0 + 2 * KVBYTES;

    const int t = threadIdx.x, wid = t >> 5, lane = t & 31;
    const int q0 = blockIdx.x * 128;
    const int bh = blockIdx.y;
    const int kz = blockIdx.z;
    const int kbase = kz * KVCHUNK;
    const int b = bh >> 3, h = bh & 7;
    const size_t rowbase = (size_t)b * Nq;
    const __nv_bfloat16* qh = qkvh + rowbase * 768 + h * HDq;
    const __nv_bfloat16* ql = qkvl + rowbase * 768 + h * HDq;

    const int ar = t >> 2, asg = t & 3;

    auto cpKV = [&](int kt, int buf) {
        const size_t go = (size_t)(kt + ar) * 768 + asg * 8;
        uint32_t kd = kB0 + buf * KVBYTES + ar * ASTRIDE + asg * 16;
        cp16(kd,      qh + go + 256);
        cp16(kd + 64, ql + go + 256);
        uint32_t vd = vB0 + buf * KVBYTES + ar * ASTRIDE + asg * 16;
        cp16(vd,      qh + go + 512);
        cp16(vd + 64, ql + go + 512);
    };

    // Q tile: 128 x 32, both planes
    #pragma unroll
    for (int i = 0; i < 2; i++) {
        const int r = ar + i * 64;
        const size_t go = (size_t)(q0 + r) * 768 + asg * 8;
        uint32_t dst = qB + r * ASTRIDE + asg * 16;
        cp16(dst, qh + go);
        cp16(dst + 64, ql + go);
    }
    cpKV(kbase, 0);
    CP_COMMIT();

    const int wm16 = wid * 16;
    const uint32_t a_row = wm16 + (lane & 15);
    const uint32_t a_off = (lane >> 4) << 4;
    const uint32_t kb_part = (lane & 7) + ((lane >> 4) << 3);
    const uint32_t kb_off  = ((lane >> 3) & 1) << 4;
    const uint32_t v_row = (lane & 7) + (((lane >> 3) & 1) << 3);
    const uint32_t v_off = (lane >> 4) << 4;

    float m0 = -1e30f, m1 = -1e30f, l0 = 0.f, l1 = 0.f;
    float O[4][4];
    #pragma unroll
    for (int j = 0; j < 4; j++)
        #pragma unroll
        for (int i = 0; i < 4; i++) O[j][i] = 0.f;

    CP_WAIT0();
    __syncthreads();

    int cur = 0;
    for (int kt = kbase; kt < kbase + KVCHUNK; kt += 64) {
        const bool more = (kt + 64 < kbase + KVCHUNK);
        if (more) { cpKV(kt + 64, cur ^ 1); CP_COMMIT(); }

        const uint32_t kC = kB0 + cur * KVBYTES;
        const uint32_t vC = vB0 + cur * KVBYTES;

        // S = Q K^T (3-term split)
        float S[8][4];
        #pragma unroll
        for (int nt = 0; nt < 8; nt++)
            #pragma unroll
            for (int i = 0; i < 4; i++) S[nt][i] = 0.f;

        #pragma unroll
        for (int ks = 0; ks < 2; ks++) {
            uint32_t ah[4], al2[4];
            uint32_t ad = qB + a_row * ASTRIDE + (ks << 5) + a_off;
            LDSM4(ah, ad);
            LDSM4(al2, ad + 64);
            #pragma unroll
            for (int gg = 0; gg < 4; gg++) {
                uint32_t bh4[4], bl4[4];
                uint32_t kd = kC + (gg * 16 + kb_part) * ASTRIDE + (ks << 5) + kb_off;
                LDSM4(bh4, kd);
                LDSM4(bl4, kd + 64);
                #pragma unroll
                for (int sub = 0; sub < 2; sub++) {
                    const int nt = gg * 2 + sub, rs = sub << 1;
                    MMA16816(S[nt], ah, bh4[rs], bh4[rs + 1]);
                    MMA16816(S[nt], ah, bl4[rs], bl4[rs + 1]);
                    MMA16816(S[nt], al2, bh4[rs], bh4[rs + 1]);
                }
            }
        }

        // online softmax (base-2)
        float mt0 = -1e30f, mt1 = -1e30f;
        #pragma unroll
        for (int nt = 0; nt < 8; nt++) {
            #pragma unroll
            for (int i = 0; i < 4; i++) S[nt][i] *= SCALE2;
            mt0 = fmaxf(mt0, fmaxf(S[nt][0], S[nt][1]));
            mt1 = fmaxf(mt1, fmaxf(S[nt][2], S[nt][3]));
        }
        mt0 = fmaxf(mt0, __shfl_xor_sync(0xffffffffu, mt0, 1));
        mt0 = fmaxf(mt0, __shfl_xor_sync(0xffffffffu, mt0, 2));
        mt1 = fmaxf(mt1, __shfl_xor_sync(0xffffffffu, mt1, 1));
        mt1 = fmaxf(mt1, __shfl_xor_sync(0xffffffffu, mt1, 2));
        const float mn0 = fmaxf(m0, mt0), mn1 = fmaxf(m1, mt1);
        const float al0 = ex2f(m0 - mn0), al1 = ex2f(m1 - mn1);
        l0 *= al0; l1 *= al1;
        #pragma unroll
        for (int j = 0; j < 4; j++) {
            O[j][0] *= al0; O[j][1] *= al0; O[j][2] *= al1; O[j][3] *= al1;
        }

        uint32_t ph01[8], ph23[8], pl01[8], pl23[8];
        float rs0 = 0.f, rs1 = 0.f;
        #pragma unroll
        for (int nt = 0; nt < 8; nt++) {
            float p0 = ex2f(S[nt][0] - mn0);
            float p1 = ex2f(S[nt][1] - mn0);
            float p2 = ex2f(S[nt][2] - mn1);
            float p3 = ex2f(S[nt][3] - mn1);
            rs0 += p0 + p1; rs1 += p2 + p3;
            split2(p0, p1, ph01[nt], pl01[nt]);
            split2(p2, p3, ph23[nt], pl23[nt]);
        }
        rs0 += __shfl_xor_sync(0xffffffffu, rs0, 1);
        rs0 += __shfl_xor_sync(0xffffffffu, rs0, 2);
        rs1 += __shfl_xor_sync(0xffffffffu, rs1, 1);
        rs1 += __shfl_xor_sync(0xffffffffu, rs1, 2);
        l0 += rs0; l1 += rs1;
        m0 = mn0; m1 = mn1;

        // O += P V (3-term split)
        #pragma unroll
        for (int s = 0; s < 4; s++) {
            uint32_t pah[4] = {ph01[2*s], ph23[2*s], ph01[2*s+1], ph23[2*s+1]};
            uint32_t pal[4] = {pl01[2*s], pl23[2*s], pl01[2*s+1], pl23[2*s+1]};
            #pragma unroll
            for (int hof = 0; hof < 2; hof++) {
                uint32_t vh4[4], vl4[4];
                uint32_t vd = vC + (s * 16 + v_row) * ASTRIDE + (hof << 5) + v_off;
                LDSM4_T(vh4, vd);
                LDSM4_T(vl4, vd + 64);
                #pragma unroll
                for (int sub = 0; sub < 2; sub++) {
                    const int j = hof * 2 + sub, rs = sub << 1;
                    MMA16816(O[j], pah, vh4[rs], vh4[rs + 1]);
                    MMA16816(O[j], pah, vl4[rs], vl4[rs + 1]);
                    MMA16816(O[j], pal, vh4[rs], vh4[rs + 1]);
                }
            }
        }
        if (more) {
            CP_WAIT0();
            __syncthreads();
            cur ^= 1;
        }
    }

    // epilogue: write UNNORMALIZED partial O (fp32) + (m, l)
    const int gr = lane >> 2, c2 = (lane & 3) << 1;
    const int row0 = q0 + wm16 + gr;
    const size_t ob = ((size_t)kz * ROWS + rowbase + row0) * Dq + h * HDq;
    #pragma unroll
    for (int j = 0; j < 4; j++) {
        const int col = j * 8 + c2;
        *(float2*)&pO[ob + col] = make_float2(O[j][0], O[j][1]);
        *(float2*)&pO[ob + 8 * (size_t)Dq + col] = make_float2(O[j][2], O[j][3]);
    }
    if ((lane & 3) == 0) {
        const size_t mi = (size_t)kz * ROWS * Hq + (rowbase + row0) * Hq + h;
        pml[mi] = make_float2(m0, l0);
        pml[mi + 8 * Hq] = make_float2(m1, l1);
    }
}

// ================= split-KV combine: 4 partials -> split planes ===============
// grid ROWS/4, 256 threads; 4 rows/block, thread handles 4 cols via float4.
__global__ void __launch_bounds__(256)
attn_combine(const float* __restrict__ pO, const float2* __restrict__ pml,
             __nv_bfloat16* __restrict__ outh, __nv_bfloat16* __restrict__ outl)
{
    const int t = threadIdx.x;
    const int row = blockIdx.x * 4 + (t >> 6);
    const int c = (t & 63) << 2;
    const int h = c >> 5;

    float2 ml[KVSPLIT];
    float4 o4[KVSPLIT];
    #pragma unroll
    for (int z = 0; z < KVSPLIT; z++) {
        ml[z] = pml[(size_t)z * ROWS * Hq + (size_t)row * Hq + h];
        o4[z] = *(const float4*)&pO[((size_t)z * ROWS + row) * Dq + c];
    }
    float M = ml[0].x;
    #pragma unroll
    for (int z = 1; z < KVSPLIT; z++) M = fmaxf(M, ml[z].x);
    float L = 0.f, ox = 0.f, oy = 0.f, oz = 0.f, ow = 0.f;
    #pragma unroll
    for (int z = 0; z < KVSPLIT; z++) {
        const float w = ex2f(ml[z].x - M);
        L += ml[z].y * w;
        ox += o4[z].x * w; oy += o4[z].y * w;
        oz += o4[z].z * w; ow += o4[z].w * w;
    }
    const float inv = 1.f / L;
    uint32_t h01, g01, h23, g23;
    split2(ox * inv, oy * inv, h01, g01);
    split2(oz * inv, ow * inv, h23, g23);
    *(uint2*)&outh[(size_t)row * Dq + c] = make_uint2(h01, h23);
    *(uint2*)&outl[(size_t)row * Dq + c] = make_uint2(g01, g23);
}

// ---------------- LayerNorm: 4 rows/block, 64 threads/row, float4/thread -----
__global__ void __launch_bounds__(256)
ln_kernel(const float* __restrict__ in, const float* __restrict__ g,
          const float* __restrict__ be, float* __restrict__ outp,
          __nv_bfloat16* __restrict__ oh, __nv_bfloat16* __restrict__ ol)
{
    __shared__ float shm[4][2];
    __shared__ float shv[4][2];
    const int t = threadIdx.x;
    const int rl = t >> 6;                 // row within block (0..3)
    const int c = (t & 63) << 2;           // col (0..252)
    const int wr = (t >> 5) & 1;           // warp-half within row
    const int row = blockIdx.x * 4 + rl;

    const float4 v = *(const float4*)&in[(size_t)row * Dq + c];
    float s = v.x + v.y + v.z + v.w;
    #pragma unroll
    for (int o = 16; o > 0; o >>= 1) s += __shfl_xor_sync(0xffffffffu, s, o);
    if ((t & 31) == 0) shm[rl][wr] = s;
    __syncthreads();
    const float mu = (shm[rl][0] + shm[rl][1]) * (1.0f / Dq);

    const float d0 = v.x - mu, d1 = v.y - mu, d2 = v.z - mu, d3 = v.w - mu;
    float s2 = d0 * d0 + d1 * d1 + d2 * d2 + d3 * d3;
    #pragma unroll
    for (int o = 16; o > 0; o >>= 1) s2 += __shfl_xor_sync(0xffffffffu, s2, o);
    if ((t & 31) == 0) shv[rl][wr] = s2;
    __syncthreads();
    const float var = (shv[rl][0] + shv[rl][1]) * (1.0f / Dq);
    const float inv = rsqrtf(var + 1e-5f);

    const float4 gg = *(const float4*)&g[c];
    const float4 bb = *(const float4*)&be[c];
    const float o0 = d0 * inv * gg.x + bb.x;
    const float o1 = d1 * inv * gg.y + bb.y;
    const float o2 = d2 * inv * gg.z + bb.z;
    const float o3 = d3 * inv * gg.w + bb.w;
    *(float4*)&outp[(size_t)row * Dq + c] = make_float4(o0, o1, o2, o3);
    uint32_t h01, g01, h23, g23;
    split2(o0, o1, h01, g01);
    split2(o2, o3, h23, g23);
    *(uint2*)&oh[(size_t)row * Dq + c] = make_uint2(h01, h23);
    *(uint2*)&ol[(size_t)row * Dq + c] = make_uint2(g01, g23);
}

// ---------------- launch ------------------------------------------------------
extern "C" void kernel_launch(void* const* d_in, const int* in_sizes, int n_in,
                              void* d_out, int out_size)
{
    const float* x      = (const float*)d_in[0];
    const float* qkv_w  = (const float*)d_in[1];
    const float* proj_w = (const float*)d_in[2];
    const float* proj_b = (const float*)d_in[3];
    const float* fc1_w  = (const float*)d_in[4];
    const float* fc1_b  = (const float*)d_in[5];
    const float* fc2_w  = (const float*)d_in[6];
    const float* fc2_b  = (const float*)d_in[7];
    const float* ln1_g  = (const float*)d_in[8];
    const float* ln1_b  = (const float*)d_in[9];
    float* out = (float*)d_out;

    __nv_bfloat16 *qwh, *qwl, *pwh, *pwl, *f1h, *f1l, *f2h, *f2l;
    __nv_bfloat16 *qkvh, *qkvl, *atth, *attl, *neth, *netl, *h1h, *h1l;
    float *proj, *net, *pO; float2* pml;
    cudaGetSymbolAddress((void**)&qwh, g_qkvwh); cudaGetSymbolAddress((void**)&qwl, g_qkvwl);
    cudaGetSymbolAddress((void**)&pwh, g_projwh);cudaGetSymbolAddress((void**)&pwl, g_projwl);
    cudaGetSymbolAddress((void**)&f1h, g_fc1wh); cudaGetSymbolAddress((void**)&f1l, g_fc1wl);
    cudaGetSymbolAddress((void**)&f2h, g_fc2wh); cudaGetSymbolAddress((void**)&f2l, g_fc2wl);
    cudaGetSymbolAddress((void**)&qkvh, g_qkvh); cudaGetSymbolAddress((void**)&qkvl, g_qkvl);
    cudaGetSymbolAddress((void**)&atth, g_atth); cudaGetSymbolAddress((void**)&attl, g_attl);
    cudaGetSymbolAddress((void**)&neth, g_neth); cudaGetSymbolAddress((void**)&netl, g_netl);
    cudaGetSymbolAddress((void**)&h1h, g_h1h);   cudaGetSymbolAddress((void**)&h1l, g_h1l);
    cudaGetSymbolAddress((void**)&proj, g_proj); cudaGetSymbolAddress((void**)&net, g_net);
    cudaGetSymbolAddress((void**)&pO, g_pO);     cudaGetSymbolAddress((void**)&pml, g_pml);

    cudaFuncSetAttribute(gemm_p<2,2,1,1>, cudaFuncAttributeMaxDynamicSharedMemorySize, GEMM_SMEM_22);
    cudaFuncSetAttribute(gemm_p<2,2,0,1>, cudaFuncAttributeMaxDynamicSharedMemorySize, GEMM_SMEM_22);
    cudaFuncSetAttribute(gemm_p<1,2,0,0>, cudaFuncAttributeMaxDynamicSharedMemorySize, GEMM_SMEM_12);
    cudaFuncSetAttribute(attn_mma, cudaFuncAttributeMaxDynamicSharedMemorySize, ATTN_SMEM);

    // 0) fused weight prep
    prep_w<<<768, 256>>>(qkv_w, proj_w, fc1_w, fc2_w,
                         qwh, qwl, pwh, pwl, f1h, f1l, f2h, f2l);
    // 1) QKV = X @ Wqkv (128x64 tiles, A fp32 reg-staged) -> planes
    gemm_p<2, 2, 1, 1><<<dim3(768 / 64, ROWS / 128), 256, GEMM_SMEM_22>>>(
        nullptr, nullptr, x, qwh, qwl, nullptr, nullptr,
        nullptr, qkvh, qkvl, ROWS, 768, Dq);
    // 2) attention split-KV: grid (16, 16, 4) -> partials
    attn_mma<<<dim3(Nq / 128, Bq * Hq, KVSPLIT), 256, ATTN_SMEM>>>(qkvh, qkvl, pO, pml);
    // 2b) combine partials -> planes
    attn_combine<<<ROWS / 4, 256>>>(pO, pml, atth, attl);
    // 3) proj + bias + residual (64x64 tiles, 256 CTAs) -> fp32
    gemm_p<1, 2, 0, 0><<<dim3(Dq / 64, ROWS / 64), 256, GEMM_SMEM_12>>>(
        atth, attl, nullptr, pwh, pwl, proj_b, x,
        proj, nullptr, nullptr, ROWS, Dq, Dq);
    // 4) LayerNorm -> fp32 shortcut + planes
    ln_kernel<<<ROWS / 4, 256>>>(proj, ln1_g, ln1_b, net, neth, netl);
    // 5) fc1 + bias (128x64 tiles) -> planes
    gemm_p<2, 2, 0, 1><<<dim3(DFFq / 64, ROWS / 128), 256, GEMM_SMEM_22>>>(
        neth, netl, nullptr, f1h, f1l, fc1_b, nullptr,
        nullptr, h1h, h1l, ROWS, DFFq, Dq);
    // 6) fc2 + bias + shortcut -> d_out fp32
    gemm_p<1, 2, 0, 0><<<dim3(Dq / 64, ROWS / 64), 256, GEMM_SMEM_12>>>(
        h1h, h1l, nullptr, f2h, f2l, fc2_b, net,
        out, nullptr, nullptr, ROWS, Dq, DFFq);
}